// round 7
// baseline (speedup 1.0000x reference)
#include <cuda_runtime.h>
#include <math.h>
#include <stdint.h>

#define Cn 512
#define Bn 64
#define Nn 1024
#define Mn 16
#define SCALE 0.04419417382415922f   // 512^-0.5

// ---------------- scratch (allocation-free) ----------------
__device__ float g_xp  [1024 * 512];    // pooled x        [B*M, C]
__device__ float g_Aq  [1024 * 512];    // A @ Wq  (via xp@Wqq + v)
__device__ float g_Ak  [1024 * 512];    // A @ Wk  (via xp@Wqk + bqWk)
__device__ float g_bqA [1024];          // xp . v   (A.bq modulo const)
__device__ float g_v   [512];           // Wq^T bq
__device__ float g_bqWk[512];           // bq @ Wk
__device__ float g_bvo [512];           // bv @ Wo^T
__device__ float g_WqT [512 * 512];
__device__ float g_WvT [512 * 512];
__device__ float g_WoT [512 * 512];
__device__ float g_Wqq [512 * 512];     // Wq^T @ Wq
__device__ float g_Wqk [512 * 512];     // Wq^T @ Wk
__device__ float g_WcT [512 * 512];     // (Wo@Wv)^T = WvT @ WoT
__device__ float g_L2  [64 * 16 * 1024];
__device__ float g_L1  [64 * 1024 * 16];
__device__ float g_xa  [1024 * 512];
__device__ float g_AFo [1024 * 512];

__device__ __forceinline__ uint32_t smem_u32(const void* p) {
    return (uint32_t)__cvta_generic_to_shared(p);
}
__device__ __forceinline__ void cp_async16(uint32_t s, const void* g) {
    asm volatile("cp.async.cg.shared.global [%0], [%1], 16;" :: "r"(s), "l"(g));
}

// ================= batched 512x512 transpose (Wq, Wv, Wo) =================
__global__ void transpose3(const float* __restrict__ Wq, const float* __restrict__ Wv,
                           const float* __restrict__ Wo, float* __restrict__ WqT,
                           float* __restrict__ WvT, float* __restrict__ WoT)
{
    __shared__ float t[32][33];
    const float* s; float* d;
    if (blockIdx.z == 0)      { s = Wq; d = WqT; }
    else if (blockIdx.z == 1) { s = Wv; d = WvT; }
    else                      { s = Wo; d = WoT; }
    const int x  = blockIdx.x * 32 + threadIdx.x;
    const int y0 = blockIdx.y * 32 + threadIdx.y;
#pragma unroll
    for (int j = 0; j < 32; j += 8)
        t[threadIdx.y + j][threadIdx.x] = s[(size_t)(y0 + j) * Cn + x];
    __syncthreads();
    const int ox  = blockIdx.y * 32 + threadIdx.x;
    const int oy0 = blockIdx.x * 32 + threadIdx.y;
#pragma unroll
    for (int j = 0; j < 32; j += 8)
        d[(size_t)(oy0 + j) * Cn + ox] = t[threadIdx.x][threadIdx.y + j];
}

// ================= pooling =================
__global__ void pool_x_kernel(const float* __restrict__ x, float* __restrict__ xp)
{
    int bm = blockIdx.x;
    int c  = threadIdx.x;
    const float* base = x + (size_t)bm * 64 * Cn + c;
    float s = 0.f;
#pragma unroll 8
    for (int t = 0; t < 64; t++) s += base[(size_t)t * Cn];
    xp[(size_t)bm * Cn + c] = s * (1.0f / 64.0f);
}

// ================= NN GEMM (dual W / dual bias / dual Y) =================
#define XS_FLOATS (64 * 36)
#define WS_FLOATS (32 * 68)
#define STAGE_FLOATS (XS_FLOATS + WS_FLOATS)
#define GEMM_SMEM (3 * STAGE_FLOATS * 4)

__global__ __launch_bounds__(256)
void gemm_nn(const float* __restrict__ X, const float* __restrict__ W0,
             const float* __restrict__ W1, const float* __restrict__ bias0,
             const float* __restrict__ bias1, float* __restrict__ Y0,
             float* __restrict__ Y1, int nsplit)
{
    extern __shared__ float sm[];
    const int tid = threadIdx.x;
    const int tx = tid & 15, ty = tid >> 4;
    const int r0 = blockIdx.y * 64;
    const float* W; const float* bias; float* Y; int n0;
    if ((int)blockIdx.x < nsplit) { W = W0; Y = Y0; bias = bias0; n0 = blockIdx.x * 64; }
    else                          { W = W1; Y = Y1; bias = bias1; n0 = (blockIdx.x - nsplit) * 64; }

    const int xlr = tid >> 2, xlk = (tid & 3) * 8;
    const int wwk = tid >> 3, wwn = (tid & 7) * 8;
    const float* gX = X + (size_t)(r0 + xlr) * Cn + xlk;
    const float* gW = W + (size_t)wwk * Cn + n0 + wwn;
    const uint32_t sbase = smem_u32(sm);
    const uint32_t xdst = sbase + (uint32_t)(xlr * 36 + xlk) * 4u;
    const uint32_t wdst = sbase + (uint32_t)(XS_FLOATS + wwk * 68 + wwn) * 4u;

#define G_LOAD(ST, K0)                                                          \
    do {                                                                        \
        const uint32_t so_ = (uint32_t)(ST) * (STAGE_FLOATS * 4u);              \
        cp_async16(xdst + so_,      gX + (K0));                                 \
        cp_async16(xdst + so_ + 16, gX + (K0) + 4);                             \
        cp_async16(wdst + so_,      gW + (size_t)(K0) * Cn);                    \
        cp_async16(wdst + so_ + 16, gW + (size_t)(K0) * Cn + 4);                \
        asm volatile("cp.async.commit_group;" ::: "memory");                    \
    } while (0)

    float acc[4][4];
#pragma unroll
    for (int i = 0; i < 4; i++)
#pragma unroll
        for (int j = 0; j < 4; j++) acc[i][j] = 0.f;

    G_LOAD(0, 0);
    G_LOAD(1, 32);

#pragma unroll 1
    for (int it = 0; it < 16; it++) {
        if (it < 15) asm volatile("cp.async.wait_group 1;" ::: "memory");
        else         asm volatile("cp.async.wait_group 0;" ::: "memory");
        __syncthreads();
        if (it + 2 < 16) G_LOAD((it + 2) % 3, (it + 2) * 32);

        const float* Xst = sm + (it % 3) * STAGE_FLOATS;
        const float* Wst = Xst + XS_FLOATS;
#pragma unroll
        for (int k4 = 0; k4 < 8; k4++) {
            float aa[4][4], bb[4][4];
#pragma unroll
            for (int i = 0; i < 4; i++) {
                float4 a = *(const float4*)(Xst + (ty * 4 + i) * 36 + k4 * 4);
                aa[i][0] = a.x; aa[i][1] = a.y; aa[i][2] = a.z; aa[i][3] = a.w;
            }
#pragma unroll
            for (int q = 0; q < 4; q++) {
                float4 b = *(const float4*)(Wst + (k4 * 4 + q) * 68 + tx * 4);
                bb[q][0] = b.x; bb[q][1] = b.y; bb[q][2] = b.z; bb[q][3] = b.w;
            }
#pragma unroll
            for (int i = 0; i < 4; i++)
#pragma unroll
                for (int j = 0; j < 4; j++)
#pragma unroll
                    for (int q = 0; q < 4; q++)
                        acc[i][j] = fmaf(aa[i][q], bb[q][j], acc[i][j]);
        }
    }
#undef G_LOAD

    float4 bi = make_float4(0.f, 0.f, 0.f, 0.f);
    if (bias) bi = *(const float4*)(bias + n0 + tx * 4);
#pragma unroll
    for (int i = 0; i < 4; i++) {
        float4 o;
        o.x = acc[i][0] + bi.x; o.y = acc[i][1] + bi.y;
        o.z = acc[i][2] + bi.z; o.w = acc[i][3] + bi.w;
        *(float4*)(Y + (size_t)(r0 + ty * 4 + i) * Cn + n0 + tx * 4) = o;
    }
}

// ================= rowdot: dst[r] = src[r,:] . vec (rows of 512) =================
__global__ void rowdot_kernel(const float* __restrict__ src, const float* __restrict__ vec,
                              float* __restrict__ dst)
{
    const int row  = blockIdx.x * 8 + (threadIdx.x >> 5);
    const int lane = threadIdx.x & 31;
    const float* sr = src + (size_t)row * Cn;
    float s = 0.f;
#pragma unroll
    for (int k = 0; k < 16; k++) s += sr[lane + 32 * k] * __ldg(&vec[lane + 32 * k]);
#pragma unroll
    for (int off = 16; off > 0; off >>= 1) s += __shfl_xor_sync(0xffffffffu, s, off);
    if (lane == 0) dst[row] = s;
}

// ================= coldot: dst[n] = sum_c M[c,n] * vec[c] =================
__global__ __launch_bounds__(256)
void coldot_kernel(const float* __restrict__ M, const float* __restrict__ vec,
                   float* __restrict__ dst)
{
    const int n = blockIdx.x * 256 + threadIdx.x;
    float s = 0.f;
#pragma unroll 8
    for (int c = 0; c < Cn; c++) s = fmaf(__ldg(&M[(size_t)c * Cn + n]), __ldg(&vec[c]), s);
    dst[n] = s;
}

// ================= fused logits: L1[b,n,m], L2[b,m,n] in one x pass =================
#define L12_SMEM (2 * 16 * 512 * 4 + 64 * 128 * 4 + 64)
__global__ __launch_bounds__(256)
void logits12_kernel(const float* __restrict__ Aq, const float* __restrict__ Ak,
                     const float* __restrict__ bqA, const float* __restrict__ x,
                     float* __restrict__ L1, float* __restrict__ L2)
{
    extern __shared__ float sm[];
    float* Aq_s = sm;
    float* Ak_s = sm + 8192;
    float* xs   = sm + 16384;
    float* bq_s = sm + 24576;
    const int b   = blockIdx.y;
    const int n0  = blockIdx.x * 128;
    const int tid = threadIdx.x;
    const int mi  = tid >> 6;
    const int ni  = tid & 63;
    const int lnr = tid >> 1;
    const int le  = tid & 1;

    {
        const float4* sq = (const float4*)(Aq + (size_t)b * 16 * Cn);
        const float4* sk = (const float4*)(Ak + (size_t)b * 16 * Cn);
        float4* dq = (float4*)Aq_s;
        float4* dk = (float4*)Ak_s;
        for (int i = tid; i < 2048; i += 256) { dq[i] = sq[i]; dk[i] = sk[i]; }
        if (tid < 16) bq_s[tid] = bqA[b * 16 + tid];
    }

    float acc1[4][2] = {}, acc2[4][2] = {};
    for (int kt = 0; kt < 8; kt++) {
        __syncthreads();
        const float* gx = x + ((size_t)b * Nn + n0 + lnr) * Cn + kt * 64 + le * 32;
#pragma unroll
        for (int f = 0; f < 8; f++) {
            float4 v = *(const float4*)(gx + f * 4);
            const int k = le * 32 + f * 4;
            xs[(k + 0) * 128 + lnr] = v.x;
            xs[(k + 1) * 128 + lnr] = v.y;
            xs[(k + 2) * 128 + lnr] = v.z;
            xs[(k + 3) * 128 + lnr] = v.w;
        }
        __syncthreads();
        const float* aqb = Aq_s + (size_t)mi * 4 * Cn + kt * 64;
        const float* akb = Ak_s + (size_t)mi * 4 * Cn + kt * 64;
#pragma unroll 8
        for (int k = 0; k < 64; k++) {
            float2 xv = *(const float2*)(xs + k * 128 + 2 * ni);
#pragma unroll
            for (int j = 0; j < 4; j++) {
                float aq = aqb[j * Cn + k];
                float ak = akb[j * Cn + k];
                acc1[j][0] = fmaf(aq, xv.x, acc1[j][0]);
                acc1[j][1] = fmaf(aq, xv.y, acc1[j][1]);
                acc2[j][0] = fmaf(ak, xv.x, acc2[j][0]);
                acc2[j][1] = fmaf(ak, xv.y, acc2[j][1]);
            }
        }
    }
#pragma unroll
    for (int j = 0; j < 4; j++) {
        float2 o = make_float2(acc2[j][0] * SCALE, acc2[j][1] * SCALE);
        *(float2*)(L2 + ((size_t)b * 16 + mi * 4 + j) * Nn + n0 + 2 * ni) = o;
    }
    {
        float4 o0, o1;
        float* p0 = (float*)&o0; float* p1 = (float*)&o1;
#pragma unroll
        for (int j = 0; j < 4; j++) {
            p0[j] = (acc1[j][0] + bq_s[mi * 4 + j]) * SCALE;
            p1[j] = (acc1[j][1] + bq_s[mi * 4 + j]) * SCALE;
        }
        *(float4*)(L1 + ((size_t)b * Nn + n0 + 2 * ni)     * 16 + mi * 4) = o0;
        *(float4*)(L1 + ((size_t)b * Nn + n0 + 2 * ni + 1) * 16 + mi * 4) = o1;
    }
}

// ================= xa = softmax_n(L2) @ x (softmax fused) =================
#define XA_SMEM (16 * 1024 * 4 + 64 * 132 * 4)
__global__ __launch_bounds__(256)
void xa_kernel(const float* __restrict__ L2, const float* __restrict__ x,
               float* __restrict__ xa)
{
    extern __shared__ float sm[];
    float* ps = sm;
    float* xs = sm + 16384;
    const int b   = blockIdx.y;
    const int c0  = blockIdx.x * 128;
    const int tid = threadIdx.x;
    const int warp = tid >> 5, lane = tid & 31;
    const int mi  = tid >> 6;
    const int ci  = tid & 63;
    const int lnr = tid >> 3;

    for (int m = warp; m < 16; m += 8) {
        const float* row = L2 + ((size_t)b * 16 + m) * Nn;
        float mx = -INFINITY;
#pragma unroll
        for (int i = 0; i < 32; i++) mx = fmaxf(mx, __ldg(row + lane + 32 * i));
#pragma unroll
        for (int off = 16; off > 0; off >>= 1)
            mx = fmaxf(mx, __shfl_xor_sync(0xffffffffu, mx, off));
        float sum = 0.f;
#pragma unroll
        for (int i = 0; i < 32; i++) {
            float e = __expf(__ldg(row + lane + 32 * i) - mx);
            ps[m * Nn + lane + 32 * i] = e;
            sum += e;
        }
#pragma unroll
        for (int off = 16; off > 0; off >>= 1)
            sum += __shfl_xor_sync(0xffffffffu, sum, off);
        const float inv = 1.0f / sum;
#pragma unroll
        for (int i = 0; i < 32; i++) ps[m * Nn + lane + 32 * i] *= inv;
    }

    float acc[4][2] = {};
    for (int nt = 0; nt < 16; nt++) {
        __syncthreads();
#pragma unroll
        for (int h = 0; h < 2; h++) {
            const int n = lnr + h * 32;
            const float* gx = x + ((size_t)b * Nn + nt * 64 + n) * Cn + c0;
#pragma unroll
            for (int q = 0; q < 4; q++) {
                const int cc = ((tid & 7) + q * 8) * 4;
                *(float4*)(xs + n * 132 + cc) = *(const float4*)(gx + cc);
            }
        }
        __syncthreads();
        const float* pb = ps + (size_t)mi * 4 * Nn + nt * 64;
#pragma unroll 8
        for (int n = 0; n < 64; n++) {
            float2 xv = *(const float2*)(xs + n * 132 + 2 * ci);
#pragma unroll
            for (int j = 0; j < 4; j++) {
                float p = pb[j * Nn + n];
                acc[j][0] = fmaf(p, xv.x, acc[j][0]);
                acc[j][1] = fmaf(p, xv.y, acc[j][1]);
            }
        }
    }
#pragma unroll
    for (int j = 0; j < 4; j++)
        *(float2*)(xa + ((size_t)b * 16 + mi * 4 + j) * Cn + c0 + 2 * ci)
            = make_float2(acc[j][0], acc[j][1]);
}

// ================= final =================
__global__ __launch_bounds__(512)
void final_kernel(const float* __restrict__ L1, const float* __restrict__ AFo,
                  const float* __restrict__ bo, float* __restrict__ out)
{
    __shared__ float afo_s[Mn * Cn];
    __shared__ float l1_s[64 * 16];
    const int b    = blockIdx.y;
    const int n0   = blockIdx.x * 64;
    const int tid  = threadIdx.x;
    const int warp = tid >> 5;
    const int lane = tid & 31;

    {
        const float4* s = (const float4*)(AFo + (size_t)b * Mn * Cn);
        float4* d = (float4*)afo_s;
        for (int i = tid; i < 2048; i += 512) d[i] = s[i];
        const float4* sl = (const float4*)(L1 + ((size_t)b * Nn + n0) * 16);
        float4* dl = (float4*)l1_s;
        if (tid < 256) dl[tid] = sl[tid];
    }
    __syncthreads();

#pragma unroll
    for (int t = 0; t < 4; t++) {
        const int tok = warp * 4 + t;
        float lg[16];
#pragma unroll
        for (int m = 0; m < Mn; m++) lg[m] = l1_s[tok * 16 + m];
        float mx = lg[0];
#pragma unroll
        for (int m = 1; m < Mn; m++) mx = fmaxf(mx, lg[m]);
        float s = 0.f;
#pragma unroll
        for (int m = 0; m < Mn; m++) { lg[m] = __expf(lg[m] - mx); s += lg[m]; }
        const float inv = 1.0f / s;

        float* orow = out + ((size_t)b * Nn + n0 + tok) * Cn;
#pragma unroll
        for (int k = 0; k < 16; k++) {
            const int c = lane + 32 * k;
            float o = 0.f;
#pragma unroll
            for (int m = 0; m < Mn; m++) o = fmaf(lg[m], afo_s[m * Cn + c], o);
            orow[c] = o * inv + __ldg(&bo[c]);
        }
    }
}

// ================= launch =================
extern "C" void kernel_launch(void* const* d_in, const int* in_sizes, int n_in,
                              void* d_out, int out_size)
{
    const float* x  = (const float*)d_in[0];
    const float* Wq = (const float*)d_in[1];
    const float* bq = (const float*)d_in[2];
    const float* Wk = (const float*)d_in[3];
    const float* bv = (const float*)d_in[6];
    const float* Wv = (const float*)d_in[5];
    const float* Wo = (const float*)d_in[7];
    const float* bo = (const float*)d_in[8];
    float* out = (float*)d_out;

    float *xp, *Aq, *Ak, *bqA, *v, *bqWk, *bvo;
    float *WqT, *WvT, *WoT, *Wqq, *Wqk, *WcT, *L1, *L2, *xa, *AFo;
    cudaGetSymbolAddress((void**)&xp,   g_xp);
    cudaGetSymbolAddress((void**)&Aq,   g_Aq);
    cudaGetSymbolAddress((void**)&Ak,   g_Ak);
    cudaGetSymbolAddress((void**)&bqA,  g_bqA);
    cudaGetSymbolAddress((void**)&v,    g_v);
    cudaGetSymbolAddress((void**)&bqWk, g_bqWk);
    cudaGetSymbolAddress((void**)&bvo,  g_bvo);
    cudaGetSymbolAddress((void**)&WqT,  g_WqT);
    cudaGetSymbolAddress((void**)&WvT,  g_WvT);
    cudaGetSymbolAddress((void**)&WoT,  g_WoT);
    cudaGetSymbolAddress((void**)&Wqq,  g_Wqq);
    cudaGetSymbolAddress((void**)&Wqk,  g_Wqk);
    cudaGetSymbolAddress((void**)&WcT,  g_WcT);
    cudaGetSymbolAddress((void**)&L1,   g_L1);
    cudaGetSymbolAddress((void**)&L2,   g_L2);
    cudaGetSymbolAddress((void**)&xa,   g_xa);
    cudaGetSymbolAddress((void**)&AFo,  g_AFo);

    static cudaStream_t sW = nullptr;
    static cudaEvent_t evFork = nullptr, evW = nullptr, evW2 = nullptr;
    static int init_done = 0;
    if (!init_done) {
        cudaFuncSetAttribute(gemm_nn,         cudaFuncAttributeMaxDynamicSharedMemorySize, GEMM_SMEM);
        cudaFuncSetAttribute(logits12_kernel, cudaFuncAttributeMaxDynamicSharedMemorySize, L12_SMEM);
        cudaFuncSetAttribute(xa_kernel,       cudaFuncAttributeMaxDynamicSharedMemorySize, XA_SMEM);
        cudaStreamCreateWithFlags(&sW, cudaStreamNonBlocking);
        cudaEventCreateWithFlags(&evFork, cudaEventDisableTiming);
        cudaEventCreateWithFlags(&evW,    cudaEventDisableTiming);
        cudaEventCreateWithFlags(&evW2,   cudaEventDisableTiming);
        init_done = 1;
    }

    // ---- fork: weight-only chain on sW ----
    cudaEventRecord(evFork, 0);
    cudaStreamWaitEvent(sW, evFork, 0);

    transpose3<<<dim3(16, 16, 3), dim3(32, 8), 0, sW>>>(Wq, Wv, Wo, WqT, WvT, WoT);
    coldot_kernel<<<2, 256, 0, sW>>>(Wq, bq, v);          // v = Wq^T bq
    coldot_kernel<<<2, 256, 0, sW>>>(Wk, bq, bqWk);       // bqWk = bq @ Wk
    rowdot_kernel<<<64, 256, 0, sW>>>(Wo, bv, bvo);       // bvo = bv @ Wo^T
    gemm_nn<<<dim3(16, 8), 256, GEMM_SMEM, sW>>>(WqT, Wq, Wk, nullptr, nullptr, Wqq, Wqk, 8);
    cudaEventRecord(evW, sW);
    gemm_nn<<<dim3(8, 8), 256, GEMM_SMEM, sW>>>(WvT, WoT, WoT, nullptr, nullptr, WcT, WcT, 8);
    cudaEventRecord(evW2, sW);

    // ---- main chain on default stream ----
    pool_x_kernel<<<1024, 512>>>(x, xp);
    cudaStreamWaitEvent(0, evW, 0);
    gemm_nn<<<dim3(16, 16), 256, GEMM_SMEM>>>(xp, Wqq, Wqk, v, bqWk, Aq, Ak, 8);
    rowdot_kernel<<<128, 256>>>(xp, v, bqA);              // bqA = xp . v (const over m dropped)
    logits12_kernel<<<dim3(8, 64), 256, L12_SMEM>>>(Aq, Ak, bqA, x, L1, L2);
    xa_kernel<<<dim3(4, 64), 256, XA_SMEM>>>(L2, x, xa);
    cudaStreamWaitEvent(0, evW2, 0);
    gemm_nn<<<dim3(8, 16), 256, GEMM_SMEM>>>(xa, WcT, WcT, bvo, bvo, AFo, AFo, 8);
    final_kernel<<<dim3(16, 64), 512>>>(L1, AFo, bo, out);
}